// round 5
// baseline (speedup 1.0000x reference)
#include <cuda_runtime.h>
#include <cuda_bf16.h>
#include <math.h>

// Problem constants
#define NN 50000
#define EE 1600000
#define GG 512
#define INF_ 128
#define HID 128
#define PROJ 256
#define NPART 128   // >= ceil(NN/512)

// ---------------- device scratch, duplicated per encoder ----------------
// All float4-cast arrays first (16B-multiple sizes); odd-sized off[] last.
struct alignas(16) EncScratch {
    float G [NN * HID];
    float Ha[NN * HID];
    float Hb[NN * HID];
    float pool[GG * HID];
    float t [GG * PROJ];
    float t2[GG * PROJ];
    float q [GG * (PROJ/2)];
    float dinv[NN];
    int   cnt[NN];
    int   csr[EE];
    int   gs[GG];
    int   ge[GG];
    int   part[NPART];
    int   off[NN + 1];        // odd size -> keep last
};
__device__ EncScratch g_e0;
__device__ EncScratch g_e1;

// ---------------- CSR build ----------------
__global__ void k_zero(int* cnt, int* gs, int* ge, int n, int g) {
    int i = blockIdx.x * blockDim.x + threadIdx.x;
    if (i < n) cnt[i] = 0;
    if (i < g) { gs[i] = n; ge[i] = 0; }
}

__global__ void k_degree(const int* __restrict__ dst, int* cnt, int e) {
    int i = blockIdx.x * blockDim.x + threadIdx.x;
    if (i < e) atomicAdd(&cnt[dst[i]], 1);
}

__global__ void k_part(const int* __restrict__ cnt, int* part, int n) {
    __shared__ int red[16];
    int i = blockIdx.x * blockDim.x + threadIdx.x;
    int v = (i < n) ? cnt[i] : 0;
    int lane = threadIdx.x & 31, wid = threadIdx.x >> 5;
    #pragma unroll
    for (int o = 16; o; o >>= 1) v += __shfl_down_sync(0xffffffffu, v, o);
    if (lane == 0) red[wid] = v;
    __syncthreads();
    if (wid == 0) {
        int s = (lane < (blockDim.x >> 5)) ? red[lane] : 0;
        #pragma unroll
        for (int o = 16; o; o >>= 1) s += __shfl_down_sync(0xffffffffu, s, o);
        if (lane == 0) part[blockIdx.x] = s;
    }
}

__global__ void k_scanpart(int* part, int nb) {
    __shared__ int sh[NPART];
    int tid = threadIdx.x;
    sh[tid] = (tid < nb) ? part[tid] : 0;
    __syncthreads();
    for (int d = 1; d < NPART; d <<= 1) {
        int v = (tid >= d) ? sh[tid - d] : 0;
        __syncthreads();
        sh[tid] += v;
        __syncthreads();
    }
    if (tid < nb) part[tid] = (tid == 0) ? 0 : sh[tid - 1];
}

__global__ void k_off(int* cnt, const int* __restrict__ part, int* off,
                      float* dinv, int n) {
    __shared__ int wsum[16];
    int i = blockIdx.x * blockDim.x + threadIdx.x;
    int lane = threadIdx.x & 31, wid = threadIdx.x >> 5;
    int nw = blockDim.x >> 5;
    int v = (i < n) ? cnt[i] : 0;
    int x = v;
    #pragma unroll
    for (int d = 1; d < 32; d <<= 1) {
        int y = __shfl_up_sync(0xffffffffu, x, d);
        if (lane >= d) x += y;
    }
    if (lane == 31) wsum[wid] = x;
    __syncthreads();
    if (wid == 0) {
        int s = (lane < nw) ? wsum[lane] : 0;
        #pragma unroll
        for (int d = 1; d < 32; d <<= 1) {
            int y = __shfl_up_sync(0xffffffffu, s, d);
            if (lane >= d) s += y;
        }
        wsum[lane] = s;
    }
    __syncthreads();
    int excl = x - v + ((wid == 0) ? 0 : wsum[wid - 1]) + part[blockIdx.x];
    if (i < n) {
        off[i]  = excl;
        dinv[i] = rsqrtf((float)(v + 1));
        cnt[i]  = excl;          // cursor for fill
        if (i == n - 1) off[n] = excl + v;
    }
}

__global__ void k_fill(const int* __restrict__ src, const int* __restrict__ dst,
                       int* cnt, int* csr, int e) {
    int i = blockIdx.x * blockDim.x + threadIdx.x;
    if (i < e) {
        int d = dst[i];
        int pos = atomicAdd(&cnt[d], 1);
        csr[pos] = src[i];
    }
}

// ---------------- tensor-core GEMM (tf32): out[M,128] = A[M,128]@W[128,128] ----
// Block: 256 threads (8 warps), tile 128 rows x 128 cols.
// Warp tile: 32 rows x 64 cols -> 2 m16 frags x 8 n8 frags, K in 16 steps of 8.
// smem stride 132 floats: A-frag banks (4g+t) and B-frag banks (4t+g) both
// bijective over the warp -> conflict-free fragment loads.
#define SW 132
__device__ __forceinline__ uint tf32r(float x) {
    uint u;
    asm("cvt.rna.tf32.f32 %0, %1;" : "=r"(u) : "f"(x));
    return u;
}

__global__ __launch_bounds__(256) void k_gemm_tc(
        const float* __restrict__ A, const float* __restrict__ W,
        float* __restrict__ out, int M) {
    extern __shared__ unsigned int smu[];
    unsigned int* As = smu;               // [128][SW]
    unsigned int* Ws = smu + 128 * SW;    // [128][SW]
    int tid = threadIdx.x;
    int rb = blockIdx.x * 128;

    for (int i = tid; i < 128 * 32; i += 256) {
        int r = i >> 5, c4 = i & 31;
        float4 v = ((const float4*)W)[r * 32 + c4];
        uint4 u = make_uint4(tf32r(v.x), tf32r(v.y), tf32r(v.z), tf32r(v.w));
        *(uint4*)(Ws + r * SW + (c4 << 2)) = u;
    }
    for (int i = tid; i < 128 * 32; i += 256) {
        int r = i >> 5, c4 = i & 31;
        float4 v = make_float4(0.f, 0.f, 0.f, 0.f);
        if (rb + r < M) v = ((const float4*)A)[(rb + r) * 32 + c4];
        uint4 u = make_uint4(tf32r(v.x), tf32r(v.y), tf32r(v.z), tf32r(v.w));
        *(uint4*)(As + r * SW + (c4 << 2)) = u;
    }
    __syncthreads();

    int lane = tid & 31, w = tid >> 5;
    int g = lane >> 2, t = lane & 3;
    int mwr = (w >> 1) * 32;
    int nwc = (w & 1) * 64;

    float acc[2][8][4];
    #pragma unroll
    for (int mf = 0; mf < 2; mf++)
        #pragma unroll
        for (int nf = 0; nf < 8; nf++)
            #pragma unroll
            for (int c = 0; c < 4; c++) acc[mf][nf][c] = 0.f;

    for (int ks = 0; ks < 16; ks++) {
        int k0 = ks * 8;
        unsigned int a[2][4];
        #pragma unroll
        for (int mf = 0; mf < 2; mf++) {
            int r0 = mwr + mf * 16;
            a[mf][0] = As[(r0 + g)     * SW + k0 + t];
            a[mf][1] = As[(r0 + g + 8) * SW + k0 + t];
            a[mf][2] = As[(r0 + g)     * SW + k0 + t + 4];
            a[mf][3] = As[(r0 + g + 8) * SW + k0 + t + 4];
        }
        unsigned int b[8][2];
        #pragma unroll
        for (int nf = 0; nf < 8; nf++) {
            int c = nwc + nf * 8 + g;
            b[nf][0] = Ws[(k0 + t)     * SW + c];
            b[nf][1] = Ws[(k0 + t + 4) * SW + c];
        }
        #pragma unroll
        for (int mf = 0; mf < 2; mf++)
            #pragma unroll
            for (int nf = 0; nf < 8; nf++)
                asm volatile(
                    "mma.sync.aligned.m16n8k8.row.col.f32.tf32.tf32.f32 "
                    "{%0,%1,%2,%3}, {%4,%5,%6,%7}, {%8,%9}, {%0,%1,%2,%3};"
                    : "+f"(acc[mf][nf][0]), "+f"(acc[mf][nf][1]),
                      "+f"(acc[mf][nf][2]), "+f"(acc[mf][nf][3])
                    : "r"(a[mf][0]), "r"(a[mf][1]), "r"(a[mf][2]), "r"(a[mf][3]),
                      "r"(b[nf][0]), "r"(b[nf][1]));
    }

    #pragma unroll
    for (int mf = 0; mf < 2; mf++) {
        int r0 = rb + mwr + mf * 16 + g;
        #pragma unroll
        for (int nf = 0; nf < 8; nf++) {
            int c = nwc + nf * 8 + t * 2;
            if (r0 < M)
                *(float2*)(out + r0 * 128 + c) =
                    make_float2(acc[mf][nf][0], acc[mf][nf][1]);
            if (r0 + 8 < M)
                *(float2*)(out + (r0 + 8) * 128 + c) =
                    make_float2(acc[mf][nf][2], acc[mf][nf][3]);
        }
    }
}

// ---------------- gather: warp per node ----------------
__global__ void k_gather(const float4* __restrict__ B, const float* __restrict__ bias,
                         const float4* __restrict__ Hres, float4* __restrict__ out,
                         const int* __restrict__ off, const int* __restrict__ csr,
                         const float* __restrict__ dinv, int n, int mode) {
    int gw = (blockIdx.x * blockDim.x + threadIdx.x) >> 5;
    if (gw >= n) return;
    int lane = threadIdx.x & 31;
    int v = gw;
    int off0 = off[v], off1 = off[v + 1];
    float dv = dinv[v];
    float4 bv = B[v * 32 + lane];
    float4 acc = make_float4(dv * bv.x, dv * bv.y, dv * bv.z, dv * bv.w);
    for (int j = off0; j < off1; j += 32) {
        int idx = j + lane;
        int u = (idx < off1) ? csr[idx] : -1;
        float wt = (u >= 0) ? dinv[u] : 0.f;
        int m = off1 - j; if (m > 32) m = 32;
        #pragma unroll 4
        for (int i = 0; i < m; i++) {
            int uu = __shfl_sync(0xffffffffu, u, i);
            float ww = __shfl_sync(0xffffffffu, wt, i);
            float4 hv = B[uu * 32 + lane];
            acc.x += ww * hv.x; acc.y += ww * hv.y;
            acc.z += ww * hv.z; acc.w += ww * hv.w;
        }
    }
    const float4* b4 = (const float4*)bias;
    float4 bb = b4[lane];
    float4 r;
    r.x = fmaxf(dv * acc.x + bb.x, 0.f);
    r.y = fmaxf(dv * acc.y + bb.y, 0.f);
    r.z = fmaxf(dv * acc.z + bb.z, 0.f);
    r.w = fmaxf(dv * acc.w + bb.w, 0.f);
    if (mode == 1) {
        float4 h = Hres[v * 32 + lane];
        r.x += h.x; r.y += h.y; r.z += h.z; r.w += h.w;
    }
    out[v * 32 + lane] = r;
}

// ---------------- pooling ----------------
__global__ void k_bounds(const int* __restrict__ batch, int* gs, int* ge, int n) {
    int i = blockIdx.x * blockDim.x + threadIdx.x;
    if (i >= n) return;
    int b = batch[i];
    if (i == 0 || batch[i - 1] != b) gs[b] = i;
    if (i == n - 1 || batch[i + 1] != b) ge[b] = i + 1;
}

__global__ void k_pool(const float4* __restrict__ H, float4* __restrict__ pool,
                       const int* __restrict__ gs, const int* __restrict__ ge, int g) {
    int gw = (blockIdx.x * blockDim.x + threadIdx.x) >> 5;
    if (gw >= g) return;
    int lane = threadIdx.x & 31;
    int s = gs[gw], e = ge[gw];
    float4 acc = make_float4(0.f, 0.f, 0.f, 0.f);
    for (int r = s; r < e; r++) {
        float4 v = H[r * 32 + lane];
        acc.x += v.x; acc.y += v.y; acc.z += v.z; acc.w += v.w;
    }
    float sc = (e > s) ? 1.0f / (float)(e - s) : 0.f;
    pool[gw * 32 + lane] = make_float4(acc.x * sc, acc.y * sc, acc.z * sc, acc.w * sc);
}

// ---------------- small GEMM: warp per row ----------------
template <int NPER>
__global__ void k_gemm_small(const float* __restrict__ A, const float* __restrict__ W,
                             const float* __restrict__ bias, float* __restrict__ out,
                             int M, int K, int N, int relu) {
    int gw = (blockIdx.x * blockDim.x + threadIdx.x) >> 5;
    if (gw >= M) return;
    int lane = threadIdx.x & 31;
    float acc[NPER];
    #pragma unroll
    for (int j = 0; j < NPER; j++) acc[j] = 0.f;
    const float* a = A + gw * K;
    for (int k = 0; k < K; k++) {
        float av = __ldg(a + k);
        const float* wr = W + k * N;
        #pragma unroll
        for (int j = 0; j < NPER; j++) acc[j] += av * __ldg(wr + lane + 32 * j);
    }
    #pragma unroll
    for (int j = 0; j < NPER; j++) {
        float v = acc[j] + bias[lane + 32 * j];
        if (relu) v = fmaxf(v, 0.f);
        out[gw * N + lane + 32 * j] = v;
    }
}

// ---------------- batchnorm ----------------
__global__ void k_bn(const float* __restrict__ x, const float* __restrict__ gamma,
                     const float* __restrict__ beta, float* __restrict__ out,
                     int rows, int cols, int relu) {
    int col = blockIdx.x;
    int tid = threadIdx.x, lane = tid & 31, wid = tid >> 5;
    __shared__ float red[8];
    __shared__ float s_m, s_inv;
    float s = 0.f, s2 = 0.f;
    for (int r = tid; r < rows; r += blockDim.x) {
        float v = x[r * cols + col];
        s += v; s2 += v * v;
    }
    #pragma unroll
    for (int o = 16; o; o >>= 1) {
        s  += __shfl_down_sync(0xffffffffu, s, o);
        s2 += __shfl_down_sync(0xffffffffu, s2, o);
    }
    if (lane == 0) { red[wid] = s; red[4 + wid] = s2; }
    __syncthreads();
    if (tid == 0) {
        float ts = red[0] + red[1] + red[2] + red[3];
        float t2 = red[4] + red[5] + red[6] + red[7];
        float m = ts / rows;
        float var = t2 / rows - m * m;
        s_m = m;
        s_inv = rsqrtf(var + 1e-5f);
    }
    __syncthreads();
    float m = s_m, inv = s_inv, ga = gamma[col], be = beta[col];
    for (int r = tid; r < rows; r += blockDim.x) {
        float v = ga * (x[r * cols + col] - m) * inv + be;
        if (relu) v = fmaxf(v, 0.f);
        out[r * cols + col] = v;
    }
}

// ---------------- host orchestration ----------------
struct HeadW {
    const float *Wp1, *bp1, *ga1, *be1, *Wp2, *bp2, *ga2, *be2;
    const float *Wq1, *bq1, *Wq2, *bq2;
};

#define GEMM_SMEM (2 * 128 * SW * sizeof(unsigned int))

static void run_encoder_and_head(cudaStream_t st, EncScratch* S,
        const float* x, const int* ei, const int* batch,
        const float* W1, const float* b1, const float* W2, const float* b2,
        const float* W3, const float* b3, const HeadW& hw,
        float* pout, float* zout, int n, int e, int g) {
    const int* src = ei;
    const int* dst = ei + e;

    int tb = 256;
    int nb512 = (n + 511) / 512;
    k_zero  <<<(n + tb - 1) / tb, tb, 0, st>>>(S->cnt, S->gs, S->ge, n, g);
    k_degree<<<(e + tb - 1) / tb, tb, 0, st>>>(dst, S->cnt, e);
    k_part  <<<nb512, 512, 0, st>>>(S->cnt, S->part, n);
    k_scanpart<<<1, NPART, 0, st>>>(S->part, nb512);
    k_off   <<<nb512, 512, 0, st>>>(S->cnt, S->part, S->off, S->dinv, n);
    k_fill  <<<(e + tb - 1) / tb, tb, 0, st>>>(src, dst, S->cnt, S->csr, e);

    int gemm_grid = (n + 127) / 128;
    int gath_grid = (n * 32 + tb - 1) / tb;

    float4* G  = (float4*)S->G;
    float4* Ha = (float4*)S->Ha;
    float4* Hb = (float4*)S->Hb;

    k_gemm_tc<<<gemm_grid, 256, GEMM_SMEM, st>>>(x, W1, S->G, n);
    k_gather<<<gath_grid, tb, 0, st>>>(G, b1, nullptr, Ha, S->off, S->csr, S->dinv, n, 0);
    k_gemm_tc<<<gemm_grid, 256, GEMM_SMEM, st>>>(S->Ha, W2, S->G, n);
    k_gather<<<gath_grid, tb, 0, st>>>(G, b2, (const float4*)Ha, Hb, S->off, S->csr, S->dinv, n, 1);
    k_gemm_tc<<<gemm_grid, 256, GEMM_SMEM, st>>>(S->Hb, W3, S->G, n);
    k_gather<<<gath_grid, tb, 0, st>>>(G, b3, (const float4*)Hb, Ha, S->off, S->csr, S->dinv, n, 1);

    k_bounds<<<(n + tb - 1) / tb, tb, 0, st>>>(batch, S->gs, S->ge, n);
    k_pool<<<(g * 32 + tb - 1) / tb, tb, 0, st>>>((const float4*)Ha, (float4*)S->pool,
                                                  S->gs, S->ge, g);

    // head
    int gw_blocks = (g * 32 + 255) / 256;
    k_gemm_small<8><<<gw_blocks, 256, 0, st>>>(S->pool, hw.Wp1, hw.bp1, S->t, g, HID, PROJ, 0);
    k_bn<<<PROJ, 128, 0, st>>>(S->t, hw.ga1, hw.be1, S->t, g, PROJ, 1);
    k_gemm_small<8><<<gw_blocks, 256, 0, st>>>(S->t, hw.Wp2, hw.bp2, S->t2, g, PROJ, PROJ, 0);
    k_bn<<<PROJ, 128, 0, st>>>(S->t2, hw.ga2, hw.be2, zout, g, PROJ, 0);
    k_gemm_small<4><<<gw_blocks, 256, 0, st>>>(zout, hw.Wq1, hw.bq1, S->q, g, PROJ, PROJ / 2, 1);
    k_gemm_small<8><<<gw_blocks, 256, 0, st>>>(S->q, hw.Wq2, hw.bq2, pout, g, PROJ / 2, PROJ, 0);
}

extern "C" void kernel_launch(void* const* d_in, const int* in_sizes, int n_in,
                              void* d_out, int out_size) {
    const float* x1  = (const float*)d_in[0];
    const int*   ei1 = (const int*)  d_in[1];
    const int*   bt1 = (const int*)  d_in[2];
    const float* x2  = (const float*)d_in[3];
    const int*   ei2 = (const int*)  d_in[4];
    const int*   bt2 = (const int*)  d_in[5];
    const float* W1  = (const float*)d_in[6];
    const float* b1  = (const float*)d_in[7];
    const float* W2  = (const float*)d_in[8];
    const float* b2  = (const float*)d_in[9];
    const float* W3  = (const float*)d_in[10];
    const float* b3  = (const float*)d_in[11];
    HeadW hw;
    hw.Wp1 = (const float*)d_in[12]; hw.bp1 = (const float*)d_in[13];
    hw.ga1 = (const float*)d_in[14]; hw.be1 = (const float*)d_in[15];
    hw.Wp2 = (const float*)d_in[16]; hw.bp2 = (const float*)d_in[17];
    hw.ga2 = (const float*)d_in[18]; hw.be2 = (const float*)d_in[19];
    hw.Wq1 = (const float*)d_in[20]; hw.bq1 = (const float*)d_in[21];
    hw.Wq2 = (const float*)d_in[22]; hw.bq2 = (const float*)d_in[23];

    int n = in_sizes[0] / INF_;
    int e = in_sizes[1] / 2;
    int g = GG;

    static bool init = false;
    static cudaStream_t s2;
    static cudaEvent_t evFork, evJoin;
    if (!init) {
        cudaStreamCreateWithFlags(&s2, cudaStreamNonBlocking);
        cudaEventCreateWithFlags(&evFork, cudaEventDisableTiming);
        cudaEventCreateWithFlags(&evJoin, cudaEventDisableTiming);
        cudaFuncSetAttribute(k_gemm_tc, cudaFuncAttributeMaxDynamicSharedMemorySize,
                             GEMM_SMEM);
        init = true;
    }

    EncScratch *S0, *S1;
    cudaGetSymbolAddress((void**)&S0, g_e0);
    cudaGetSymbolAddress((void**)&S1, g_e1);

    float* out = (float*)d_out;
    float* p1 = out;
    float* p2 = out + g * PROJ;
    float* z1 = out + 2 * g * PROJ;
    float* z2 = out + 3 * g * PROJ;

    // fork
    cudaEventRecord(evFork, 0);
    cudaStreamWaitEvent(s2, evFork, 0);

    run_encoder_and_head(0,  S0, x1, ei1, bt1, W1, b1, W2, b2, W3, b3, hw, p1, z1, n, e, g);
    run_encoder_and_head(s2, S1, x2, ei2, bt2, W1, b1, W2, b2, W3, b3, hw, p2, z2, n, e, g);

    // join
    cudaEventRecord(evJoin, s2);
    cudaStreamWaitEvent(0, evJoin, 0);
}

// round 7
// speedup vs baseline: 1.3176x; 1.3176x over previous
#include <cuda_runtime.h>
#include <cuda_bf16.h>
#include <math.h>

// Problem constants
#define NN 50000
#define EE 1600000
#define GG 512
#define INF_ 128
#define HID 128
#define PROJ 256
#define NPART 128   // >= ceil(NN/512)

// ---------------- device scratch, duplicated per encoder ----------------
// All float4-cast arrays first (16B-multiple sizes); odd-sized off[] last.
struct alignas(16) EncScratch {
    float G [NN * HID];
    float Ha[NN * HID];
    float Hb[NN * HID];
    float pool[GG * HID];
    float t [GG * PROJ];
    float t2[GG * PROJ];
    float q [GG * (PROJ/2)];
    float dinv[NN];
    int   cnt[NN];
    int   csr[EE];
    int   gs[GG];
    int   ge[GG];
    int   part[NPART];
    int   off[NN + 1];        // odd size -> keep last
};
__device__ EncScratch g_e0;
__device__ EncScratch g_e1;

// ---------------- CSR build ----------------
__global__ void k_zero(int* cnt, int* gs, int* ge, int n, int g) {
    int i = blockIdx.x * blockDim.x + threadIdx.x;
    if (i < n) cnt[i] = 0;
    if (i < g) { gs[i] = n; ge[i] = 0; }
}

__global__ void k_degree(const int* __restrict__ dst, int* cnt, int e) {
    int i = blockIdx.x * blockDim.x + threadIdx.x;
    if (i < e) atomicAdd(&cnt[dst[i]], 1);
}

__global__ void k_part(const int* __restrict__ cnt, int* part, int n) {
    __shared__ int red[16];
    int i = blockIdx.x * blockDim.x + threadIdx.x;
    int v = (i < n) ? cnt[i] : 0;
    int lane = threadIdx.x & 31, wid = threadIdx.x >> 5;
    #pragma unroll
    for (int o = 16; o; o >>= 1) v += __shfl_down_sync(0xffffffffu, v, o);
    if (lane == 0) red[wid] = v;
    __syncthreads();
    if (wid == 0) {
        int s = (lane < (blockDim.x >> 5)) ? red[lane] : 0;
        #pragma unroll
        for (int o = 16; o; o >>= 1) s += __shfl_down_sync(0xffffffffu, s, o);
        if (lane == 0) part[blockIdx.x] = s;
    }
}

__global__ void k_scanpart(int* part, int nb) {
    __shared__ int sh[NPART];
    int tid = threadIdx.x;
    sh[tid] = (tid < nb) ? part[tid] : 0;
    __syncthreads();
    for (int d = 1; d < NPART; d <<= 1) {
        int v = (tid >= d) ? sh[tid - d] : 0;
        __syncthreads();
        sh[tid] += v;
        __syncthreads();
    }
    if (tid < nb) part[tid] = (tid == 0) ? 0 : sh[tid - 1];
}

__global__ void k_off(int* cnt, const int* __restrict__ part, int* off,
                      float* dinv, int n) {
    __shared__ int wsum[16];
    int i = blockIdx.x * blockDim.x + threadIdx.x;
    int lane = threadIdx.x & 31, wid = threadIdx.x >> 5;
    int nw = blockDim.x >> 5;
    int v = (i < n) ? cnt[i] : 0;
    int x = v;
    #pragma unroll
    for (int d = 1; d < 32; d <<= 1) {
        int y = __shfl_up_sync(0xffffffffu, x, d);
        if (lane >= d) x += y;
    }
    if (lane == 31) wsum[wid] = x;
    __syncthreads();
    if (wid == 0) {
        int s = (lane < nw) ? wsum[lane] : 0;
        #pragma unroll
        for (int d = 1; d < 32; d <<= 1) {
            int y = __shfl_up_sync(0xffffffffu, s, d);
            if (lane >= d) s += y;
        }
        wsum[lane] = s;
    }
    __syncthreads();
    int excl = x - v + ((wid == 0) ? 0 : wsum[wid - 1]) + part[blockIdx.x];
    if (i < n) {
        off[i]  = excl;
        dinv[i] = rsqrtf((float)(v + 1));
        cnt[i]  = excl;          // cursor for fill
        if (i == n - 1) off[n] = excl + v;
    }
}

__global__ void k_fill(const int* __restrict__ src, const int* __restrict__ dst,
                       int* cnt, int* csr, int e) {
    int i = blockIdx.x * blockDim.x + threadIdx.x;
    if (i < e) {
        int d = dst[i];
        int pos = atomicAdd(&cnt[d], 1);
        csr[pos] = src[i];
    }
}

// ---------------- packed-f32x2 GEMM: out[M,128] = A[M,128]@W[128,128] -------
// 256 threads, 64-row tile. K processed in pairs; W stored interleaved in smem
// as (W[2k][c], W[2k+1][c]) so both A and W feed fma.rn.f32x2 directly.
// Accumulator lanes hold (sum over even k, sum over odd k); one hadd at end.
__device__ __forceinline__ void fma_f32x2(unsigned long long& d,
                                          unsigned long long a,
                                          unsigned long long b) {
    asm("fma.rn.f32x2 %0, %1, %2, %0;" : "+l"(d) : "l"(a), "l"(b));
}

__global__ __launch_bounds__(256) void k_gemm_p2(
        const float* __restrict__ A, const float* __restrict__ W,
        float* __restrict__ out, int M) {
    extern __shared__ float sm[];
    float2* Ws2 = (float2*)sm;            // [64][128] float2 = 64KB
    float*  As  = sm + 64 * 128 * 2;      // [64][128] float  = 32KB
    int tid = threadIdx.x;

    // Load W interleaved by k-pairs: Ws2[kp][c] = (W[2kp][c], W[2kp+1][c])
    for (int i = tid; i < 64 * 32; i += 256) {
        int kp = i >> 5, c4 = i & 31;
        float4 w0 = ((const float4*)W)[(2 * kp)     * 32 + c4];
        float4 w1 = ((const float4*)W)[(2 * kp + 1) * 32 + c4];
        float2* dstp = Ws2 + kp * 128 + (c4 << 2);
        dstp[0] = make_float2(w0.x, w1.x);
        dstp[1] = make_float2(w0.y, w1.y);
        dstp[2] = make_float2(w0.z, w1.z);
        dstp[3] = make_float2(w0.w, w1.w);
    }
    int rowbase = blockIdx.x * 64;
    for (int i = tid; i < 64 * 32; i += 256) {
        int r = i >> 5, c4 = i & 31;
        float4 v = make_float4(0.f, 0.f, 0.f, 0.f);
        if (rowbase + r < M) v = ((const float4*)A)[(rowbase + r) * 32 + c4];
        *(float4*)(As + r * 128 + (c4 << 2)) = v;
    }
    __syncthreads();

    int lane = tid & 31, w = tid >> 5;
    unsigned long long acc[8][4];
    #pragma unroll
    for (int r = 0; r < 8; r++)
        #pragma unroll
        for (int j = 0; j < 4; j++) acc[r][j] = 0ull;   // (0.0f, 0.0f)

    const unsigned long long* Wsu = (const unsigned long long*)Ws2;
    #pragma unroll 4
    for (int kp = 0; kp < 64; kp++) {
        unsigned long long w2[4];
        #pragma unroll
        for (int j = 0; j < 4; j++) w2[j] = Wsu[kp * 128 + lane + 32 * j];
        #pragma unroll
        for (int r = 0; r < 8; r++) {
            unsigned long long a2 =
                *(const unsigned long long*)(As + (w + r * 8) * 128 + 2 * kp);
            #pragma unroll
            for (int j = 0; j < 4; j++) fma_f32x2(acc[r][j], a2, w2[j]);
        }
    }

    #pragma unroll
    for (int r = 0; r < 8; r++) {
        int row = rowbase + w + r * 8;
        if (row < M) {
            #pragma unroll
            for (int j = 0; j < 4; j++) {
                unsigned long long u = acc[r][j];
                float lo = __uint_as_float((unsigned int)(u & 0xffffffffu));
                float hi = __uint_as_float((unsigned int)(u >> 32));
                out[row * 128 + lane + 32 * j] = lo + hi;
            }
        }
    }
}
#define GEMM_SMEM ((64 * 128 * 2 + 64 * 128) * sizeof(float))

// ---------------- gather: warp per node ----------------
__global__ void k_gather(const float4* __restrict__ B, const float* __restrict__ bias,
                         const float4* __restrict__ Hres, float4* __restrict__ out,
                         const int* __restrict__ off, const int* __restrict__ csr,
                         const float* __restrict__ dinv, int n, int mode) {
    int gw = (blockIdx.x * blockDim.x + threadIdx.x) >> 5;
    if (gw >= n) return;
    int lane = threadIdx.x & 31;
    int v = gw;
    int off0 = off[v], off1 = off[v + 1];
    float dv = dinv[v];
    float4 bv = B[v * 32 + lane];
    float4 acc = make_float4(dv * bv.x, dv * bv.y, dv * bv.z, dv * bv.w);
    for (int j = off0; j < off1; j += 32) {
        int idx = j + lane;
        int u = (idx < off1) ? csr[idx] : -1;
        float wt = (u >= 0) ? dinv[u] : 0.f;
        int m = off1 - j; if (m > 32) m = 32;
        #pragma unroll 4
        for (int i = 0; i < m; i++) {
            int uu = __shfl_sync(0xffffffffu, u, i);
            float ww = __shfl_sync(0xffffffffu, wt, i);
            float4 hv = B[uu * 32 + lane];
            acc.x += ww * hv.x; acc.y += ww * hv.y;
            acc.z += ww * hv.z; acc.w += ww * hv.w;
        }
    }
    const float4* b4 = (const float4*)bias;
    float4 bb = b4[lane];
    float4 r;
    r.x = fmaxf(dv * acc.x + bb.x, 0.f);
    r.y = fmaxf(dv * acc.y + bb.y, 0.f);
    r.z = fmaxf(dv * acc.z + bb.z, 0.f);
    r.w = fmaxf(dv * acc.w + bb.w, 0.f);
    if (mode == 1) {
        float4 h = Hres[v * 32 + lane];
        r.x += h.x; r.y += h.y; r.z += h.z; r.w += h.w;
    }
    out[v * 32 + lane] = r;
}

// ---------------- pooling ----------------
__global__ void k_bounds(const int* __restrict__ batch, int* gs, int* ge, int n) {
    int i = blockIdx.x * blockDim.x + threadIdx.x;
    if (i >= n) return;
    int b = batch[i];
    if (i == 0 || batch[i - 1] != b) gs[b] = i;
    if (i == n - 1 || batch[i + 1] != b) ge[b] = i + 1;
}

__global__ void k_pool(const float4* __restrict__ H, float4* __restrict__ pool,
                       const int* __restrict__ gs, const int* __restrict__ ge, int g) {
    int gw = (blockIdx.x * blockDim.x + threadIdx.x) >> 5;
    if (gw >= g) return;
    int lane = threadIdx.x & 31;
    int s = gs[gw], e = ge[gw];
    float4 acc = make_float4(0.f, 0.f, 0.f, 0.f);
    for (int r = s; r < e; r++) {
        float4 v = H[r * 32 + lane];
        acc.x += v.x; acc.y += v.y; acc.z += v.z; acc.w += v.w;
    }
    float sc = (e > s) ? 1.0f / (float)(e - s) : 0.f;
    pool[gw * 32 + lane] = make_float4(acc.x * sc, acc.y * sc, acc.z * sc, acc.w * sc);
}

// ---------------- small GEMM: warp per row ----------------
template <int NPER>
__global__ void k_gemm_small(const float* __restrict__ A, const float* __restrict__ W,
                             const float* __restrict__ bias, float* __restrict__ out,
                             int M, int K, int N, int relu) {
    int gw = (blockIdx.x * blockDim.x + threadIdx.x) >> 5;
    if (gw >= M) return;
    int lane = threadIdx.x & 31;
    float acc[NPER];
    #pragma unroll
    for (int j = 0; j < NPER; j++) acc[j] = 0.f;
    const float* a = A + gw * K;
    for (int k = 0; k < K; k++) {
        float av = __ldg(a + k);
        const float* wr = W + k * N;
        #pragma unroll
        for (int j = 0; j < NPER; j++) acc[j] += av * __ldg(wr + lane + 32 * j);
    }
    #pragma unroll
    for (int j = 0; j < NPER; j++) {
        float v = acc[j] + bias[lane + 32 * j];
        if (relu) v = fmaxf(v, 0.f);
        out[gw * N + lane + 32 * j] = v;
    }
}

// ---------------- batchnorm ----------------
__global__ void k_bn(const float* __restrict__ x, const float* __restrict__ gamma,
                     const float* __restrict__ beta, float* __restrict__ out,
                     int rows, int cols, int relu) {
    int col = blockIdx.x;
    int tid = threadIdx.x, lane = tid & 31, wid = tid >> 5;
    __shared__ float red[8];
    __shared__ float s_m, s_inv;
    float s = 0.f, s2 = 0.f;
    for (int r = tid; r < rows; r += blockDim.x) {
        float v = x[r * cols + col];
        s += v; s2 += v * v;
    }
    #pragma unroll
    for (int o = 16; o; o >>= 1) {
        s  += __shfl_down_sync(0xffffffffu, s, o);
        s2 += __shfl_down_sync(0xffffffffu, s2, o);
    }
    if (lane == 0) { red[wid] = s; red[4 + wid] = s2; }
    __syncthreads();
    if (tid == 0) {
        float ts = red[0] + red[1] + red[2] + red[3];
        float t2 = red[4] + red[5] + red[6] + red[7];
        float m = ts / rows;
        float var = t2 / rows - m * m;
        s_m = m;
        s_inv = rsqrtf(var + 1e-5f);
    }
    __syncthreads();
    float m = s_m, inv = s_inv, ga = gamma[col], be = beta[col];
    for (int r = tid; r < rows; r += blockDim.x) {
        float v = ga * (x[r * cols + col] - m) * inv + be;
        if (relu) v = fmaxf(v, 0.f);
        out[r * cols + col] = v;
    }
}

// ---------------- host orchestration ----------------
struct HeadW {
    const float *Wp1, *bp1, *ga1, *be1, *Wp2, *bp2, *ga2, *be2;
    const float *Wq1, *bq1, *Wq2, *bq2;
};

static void run_encoder_and_head(cudaStream_t st, EncScratch* S,
        const float* x, const int* ei, const int* batch,
        const float* W1, const float* b1, const float* W2, const float* b2,
        const float* W3, const float* b3, const HeadW& hw,
        float* pout, float* zout, int n, int e, int g) {
    const int* src = ei;
    const int* dst = ei + e;

    int tb = 256;
    int nb512 = (n + 511) / 512;
    k_zero  <<<(n + tb - 1) / tb, tb, 0, st>>>(S->cnt, S->gs, S->ge, n, g);
    k_degree<<<(e + tb - 1) / tb, tb, 0, st>>>(dst, S->cnt, e);
    k_part  <<<nb512, 512, 0, st>>>(S->cnt, S->part, n);
    k_scanpart<<<1, NPART, 0, st>>>(S->part, nb512);
    k_off   <<<nb512, 512, 0, st>>>(S->cnt, S->part, S->off, S->dinv, n);
    k_fill  <<<(e + tb - 1) / tb, tb, 0, st>>>(src, dst, S->cnt, S->csr, e);

    int gemm_grid = (n + 63) / 64;
    int gath_grid = (n * 32 + tb - 1) / tb;

    float4* G  = (float4*)S->G;
    float4* Ha = (float4*)S->Ha;
    float4* Hb = (float4*)S->Hb;

    k_gemm_p2<<<gemm_grid, 256, GEMM_SMEM, st>>>(x, W1, S->G, n);
    k_gather<<<gath_grid, tb, 0, st>>>(G, b1, nullptr, Ha, S->off, S->csr, S->dinv, n, 0);
    k_gemm_p2<<<gemm_grid, 256, GEMM_SMEM, st>>>(S->Ha, W2, S->G, n);
    k_gather<<<gath_grid, tb, 0, st>>>(G, b2, (const float4*)Ha, Hb, S->off, S->csr, S->dinv, n, 1);
    k_gemm_p2<<<gemm_grid, 256, GEMM_SMEM, st>>>(S->Hb, W3, S->G, n);
    k_gather<<<gath_grid, tb, 0, st>>>(G, b3, (const float4*)Hb, Ha, S->off, S->csr, S->dinv, n, 1);

    k_bounds<<<(n + tb - 1) / tb, tb, 0, st>>>(batch, S->gs, S->ge, n);
    k_pool<<<(g * 32 + tb - 1) / tb, tb, 0, st>>>((const float4*)Ha, (float4*)S->pool,
                                                  S->gs, S->ge, g);

    // head
    int gw_blocks = (g * 32 + 255) / 256;
    k_gemm_small<8><<<gw_blocks, 256, 0, st>>>(S->pool, hw.Wp1, hw.bp1, S->t, g, HID, PROJ, 0);
    k_bn<<<PROJ, 128, 0, st>>>(S->t, hw.ga1, hw.be1, S->t, g, PROJ, 1);
    k_gemm_small<8><<<gw_blocks, 256, 0, st>>>(S->t, hw.Wp2, hw.bp2, S->t2, g, PROJ, PROJ, 0);
    k_bn<<<PROJ, 128, 0, st>>>(S->t2, hw.ga2, hw.be2, zout, g, PROJ, 0);
    k_gemm_small<4><<<gw_blocks, 256, 0, st>>>(zout, hw.Wq1, hw.bq1, S->q, g, PROJ, PROJ / 2, 1);
    k_gemm_small<8><<<gw_blocks, 256, 0, st>>>(S->q, hw.Wq2, hw.bq2, pout, g, PROJ / 2, PROJ, 0);
}

extern "C" void kernel_launch(void* const* d_in, const int* in_sizes, int n_in,
                              void* d_out, int out_size) {
    const float* x1  = (const float*)d_in[0];
    const int*   ei1 = (const int*)  d_in[1];
    const int*   bt1 = (const int*)  d_in[2];
    const float* x2  = (const float*)d_in[3];
    const int*   ei2 = (const int*)  d_in[4];
    const int*   bt2 = (const int*)  d_in[5];
    const float* W1  = (const float*)d_in[6];
    const float* b1  = (const float*)d_in[7];
    const float* W2  = (const float*)d_in[8];
    const float* b2  = (const float*)d_in[9];
    const float* W3  = (const float*)d_in[10];
    const float* b3  = (const float*)d_in[11];
    HeadW hw;
    hw.Wp1 = (const float*)d_in[12]; hw.bp1 = (const float*)d_in[13];
    hw.ga1 = (const float*)d_in[14]; hw.be1 = (const float*)d_in[15];
    hw.Wp2 = (const float*)d_in[16]; hw.bp2 = (const float*)d_in[17];
    hw.ga2 = (const float*)d_in[18]; hw.be2 = (const float*)d_in[19];
    hw.Wq1 = (const float*)d_in[20]; hw.bq1 = (const float*)d_in[21];
    hw.Wq2 = (const float*)d_in[22]; hw.bq2 = (const float*)d_in[23];

    int n = in_sizes[0] / INF_;
    int e = in_sizes[1] / 2;
    int g = GG;

    static bool init = false;
    static cudaStream_t s2;
    static cudaEvent_t evFork, evJoin;
    if (!init) {
        cudaStreamCreateWithFlags(&s2, cudaStreamNonBlocking);
        cudaEventCreateWithFlags(&evFork, cudaEventDisableTiming);
        cudaEventCreateWithFlags(&evJoin, cudaEventDisableTiming);
        cudaFuncSetAttribute(k_gemm_p2, cudaFuncAttributeMaxDynamicSharedMemorySize,
                             GEMM_SMEM);
        init = true;
    }

    EncScratch *S0, *S1;
    cudaGetSymbolAddress((void**)&S0, g_e0);
    cudaGetSymbolAddress((void**)&S1, g_e1);

    float* out = (float*)d_out;
    float* p1 = out;
    float* p2 = out + g * PROJ;
    float* z1 = out + 2 * g * PROJ;
    float* z2 = out + 3 * g * PROJ;

    // fork
    cudaEventRecord(evFork, 0);
    cudaStreamWaitEvent(s2, evFork, 0);

    run_encoder_and_head(0,  S0, x1, ei1, bt1, W1, b1, W2, b2, W3, b3, hw, p1, z1, n, e, g);
    run_encoder_and_head(s2, S1, x2, ei2, bt2, W1, b1, W2, b2, W3, b3, hw, p2, z2, n, e, g);

    // join
    cudaEventRecord(evJoin, s2);
    cudaStreamWaitEvent(0, evJoin, 0);
}

// round 9
// speedup vs baseline: 1.4552x; 1.1044x over previous
#include <cuda_runtime.h>
#include <cuda_bf16.h>
#include <cuda_fp16.h>
#include <math.h>

// Problem constants
#define NN 50000
#define EE 1600000
#define GG 512
#define INF_ 128
#define HID 128
#define PROJ 256
#define NPART 128   // >= ceil(NN/512)

// ---------------- device scratch, duplicated per encoder ----------------
// All float4/uint2-cast arrays first (16B-multiple sizes); odd-sized off[] last.
struct alignas(16) EncScratch {
    __half Gh[NN * HID];      // fp16 pre-aggregation features (gather input)
    float Ha[NN * HID];
    float Hb[NN * HID];
    float pool[GG * HID];
    float t [GG * PROJ];
    float t2[GG * PROJ];
    float q [GG * (PROJ/2)];
    float dinv[NN];
    int   cnt[NN];
    int   csr[EE];
    int   gs[GG];
    int   ge[GG];
    int   part[NPART];
    int   off[NN + 1];        // odd size -> keep last
};
__device__ EncScratch g_e0;
__device__ EncScratch g_e1;

// ---------------- CSR build ----------------
__global__ void k_zero(int* cnt, int* gs, int* ge, int n, int g) {
    int i = blockIdx.x * blockDim.x + threadIdx.x;
    if (i < n) cnt[i] = 0;
    if (i < g) { gs[i] = n; ge[i] = 0; }
}

__global__ void k_degree(const int* __restrict__ dst, int* cnt, int e) {
    int i = blockIdx.x * blockDim.x + threadIdx.x;
    if (i < e) atomicAdd(&cnt[dst[i]], 1);
}

__global__ void k_part(const int* __restrict__ cnt, int* part, int n) {
    __shared__ int red[16];
    int i = blockIdx.x * blockDim.x + threadIdx.x;
    int v = (i < n) ? cnt[i] : 0;
    int lane = threadIdx.x & 31, wid = threadIdx.x >> 5;
    #pragma unroll
    for (int o = 16; o; o >>= 1) v += __shfl_down_sync(0xffffffffu, v, o);
    if (lane == 0) red[wid] = v;
    __syncthreads();
    if (wid == 0) {
        int s = (lane < (blockDim.x >> 5)) ? red[lane] : 0;
        #pragma unroll
        for (int o = 16; o; o >>= 1) s += __shfl_down_sync(0xffffffffu, s, o);
        if (lane == 0) part[blockIdx.x] = s;
    }
}

__global__ void k_scanpart(int* part, int nb) {
    __shared__ int sh[NPART];
    int tid = threadIdx.x;
    sh[tid] = (tid < nb) ? part[tid] : 0;
    __syncthreads();
    for (int d = 1; d < NPART; d <<= 1) {
        int v = (tid >= d) ? sh[tid - d] : 0;
        __syncthreads();
        sh[tid] += v;
        __syncthreads();
    }
    if (tid < nb) part[tid] = (tid == 0) ? 0 : sh[tid - 1];
}

__global__ void k_off(int* cnt, const int* __restrict__ part, int* off,
                      float* dinv, int n) {
    __shared__ int wsum[16];
    int i = blockIdx.x * blockDim.x + threadIdx.x;
    int lane = threadIdx.x & 31, wid = threadIdx.x >> 5;
    int nw = blockDim.x >> 5;
    int v = (i < n) ? cnt[i] : 0;
    int x = v;
    #pragma unroll
    for (int d = 1; d < 32; d <<= 1) {
        int y = __shfl_up_sync(0xffffffffu, x, d);
        if (lane >= d) x += y;
    }
    if (lane == 31) wsum[wid] = x;
    __syncthreads();
    if (wid == 0) {
        int s = (lane < nw) ? wsum[lane] : 0;
        #pragma unroll
        for (int d = 1; d < 32; d <<= 1) {
            int y = __shfl_up_sync(0xffffffffu, s, d);
            if (lane >= d) s += y;
        }
        wsum[lane] = s;
    }
    __syncthreads();
    int excl = x - v + ((wid == 0) ? 0 : wsum[wid - 1]) + part[blockIdx.x];
    if (i < n) {
        off[i]  = excl;
        dinv[i] = rsqrtf((float)(v + 1));
        cnt[i]  = excl;          // cursor for fill
        if (i == n - 1) off[n] = excl + v;
    }
}

__global__ void k_fill(const int* __restrict__ src, const int* __restrict__ dst,
                       int* cnt, int* csr, int e) {
    int i = blockIdx.x * blockDim.x + threadIdx.x;
    if (i < e) {
        int d = dst[i];
        int pos = atomicAdd(&cnt[d], 1);
        csr[pos] = src[i];
    }
}

// ---------------- packed-f32x2 GEMM: out_h[M,128] = A[M,128]@W[128,128] -----
// 256 threads, 64-row tile. K processed in pairs; W stored interleaved in smem
// as (W[2k][c], W[2k+1][c]) so both A and W feed fma.rn.f32x2 directly.
// Epilogue converts to fp16 for the gather (halves per-edge L2 traffic).
__device__ __forceinline__ void fma_f32x2(unsigned long long& d,
                                          unsigned long long a,
                                          unsigned long long b) {
    asm("fma.rn.f32x2 %0, %1, %2, %0;" : "+l"(d) : "l"(a), "l"(b));
}

__global__ __launch_bounds__(256) void k_gemm_p2(
        const float* __restrict__ A, const float* __restrict__ W,
        __half* __restrict__ out, int M) {
    extern __shared__ float sm[];
    float2* Ws2 = (float2*)sm;            // [64][128] float2 = 64KB
    float*  As  = sm + 64 * 128 * 2;      // [64][128] float  = 32KB
    int tid = threadIdx.x;

    // Load W interleaved by k-pairs: Ws2[kp][c] = (W[2kp][c], W[2kp+1][c])
    for (int i = tid; i < 64 * 32; i += 256) {
        int kp = i >> 5, c4 = i & 31;
        float4 w0 = ((const float4*)W)[(2 * kp)     * 32 + c4];
        float4 w1 = ((const float4*)W)[(2 * kp + 1) * 32 + c4];
        float2* dstp = Ws2 + kp * 128 + (c4 << 2);
        dstp[0] = make_float2(w0.x, w1.x);
        dstp[1] = make_float2(w0.y, w1.y);
        dstp[2] = make_float2(w0.z, w1.z);
        dstp[3] = make_float2(w0.w, w1.w);
    }
    int rowbase = blockIdx.x * 64;
    for (int i = tid; i < 64 * 32; i += 256) {
        int r = i >> 5, c4 = i & 31;
        float4 v = make_float4(0.f, 0.f, 0.f, 0.f);
        if (rowbase + r < M) v = ((const float4*)A)[(rowbase + r) * 32 + c4];
        *(float4*)(As + r * 128 + (c4 << 2)) = v;
    }
    __syncthreads();

    int lane = tid & 31, w = tid >> 5;
    unsigned long long acc[8][4];
    #pragma unroll
    for (int r = 0; r < 8; r++)
        #pragma unroll
        for (int j = 0; j < 4; j++) acc[r][j] = 0ull;   // (0.0f, 0.0f)

    const unsigned long long* Wsu = (const unsigned long long*)Ws2;
    #pragma unroll 4
    for (int kp = 0; kp < 64; kp++) {
        unsigned long long w2[4];
        #pragma unroll
        for (int j = 0; j < 4; j++) w2[j] = Wsu[kp * 128 + lane + 32 * j];
        #pragma unroll
        for (int r = 0; r < 8; r++) {
            unsigned long long a2 =
                *(const unsigned long long*)(As + (w + r * 8) * 128 + 2 * kp);
            #pragma unroll
            for (int j = 0; j < 4; j++) fma_f32x2(acc[r][j], a2, w2[j]);
        }
    }

    #pragma unroll
    for (int r = 0; r < 8; r++) {
        int row = rowbase + w + r * 8;
        if (row < M) {
            #pragma unroll
            for (int j = 0; j < 4; j++) {
                unsigned long long u = acc[r][j];
                float lo = __uint_as_float((unsigned int)(u & 0xffffffffu));
                float hi = __uint_as_float((unsigned int)(u >> 32));
                out[row * 128 + lane + 32 * j] = __float2half_rn(lo + hi);
            }
        }
    }
}
#define GEMM_SMEM ((64 * 128 * 2 + 64 * 128) * sizeof(float))

// ---------------- gather: warp per node, fp16 neighbor features ----------------
// B layout: [n][32] uint2; lane's uint2 = features 4*lane..4*lane+3 as halfs.
__global__ void k_gather(const uint2* __restrict__ B, const float* __restrict__ bias,
                         const float4* __restrict__ Hres, float4* __restrict__ out,
                         const int* __restrict__ off, const int* __restrict__ csr,
                         const float* __restrict__ dinv, int n, int mode) {
    int gw = (blockIdx.x * blockDim.x + threadIdx.x) >> 5;
    if (gw >= n) return;
    int lane = threadIdx.x & 31;
    int v = gw;
    int off0 = off[v], off1 = off[v + 1];
    float dv = dinv[v];
    uint2 bu = B[v * 32 + lane];
    const __half2* bh = (const __half2*)&bu;
    float2 b0 = __half22float2(bh[0]);
    float2 b1 = __half22float2(bh[1]);
    float4 acc = make_float4(dv * b0.x, dv * b0.y, dv * b1.x, dv * b1.y);
    for (int j = off0; j < off1; j += 32) {
        int idx = j + lane;
        int u = (idx < off1) ? csr[idx] : -1;
        float wt = (u >= 0) ? dinv[u] : 0.f;
        int m = off1 - j; if (m > 32) m = 32;
        #pragma unroll 4
        for (int i = 0; i < m; i++) {
            int uu = __shfl_sync(0xffffffffu, u, i);
            float ww = __shfl_sync(0xffffffffu, wt, i);
            uint2 hu = B[uu * 32 + lane];
            const __half2* hh = (const __half2*)&hu;
            float2 f0 = __half22float2(hh[0]);
            float2 f1 = __half22float2(hh[1]);
            acc.x += ww * f0.x; acc.y += ww * f0.y;
            acc.z += ww * f1.x; acc.w += ww * f1.y;
        }
    }
    const float4* b4 = (const float4*)bias;
    float4 bb = b4[lane];
    float4 r;
    r.x = fmaxf(dv * acc.x + bb.x, 0.f);
    r.y = fmaxf(dv * acc.y + bb.y, 0.f);
    r.z = fmaxf(dv * acc.z + bb.z, 0.f);
    r.w = fmaxf(dv * acc.w + bb.w, 0.f);
    if (mode == 1) {
        float4 h = Hres[v * 32 + lane];
        r.x += h.x; r.y += h.y; r.z += h.z; r.w += h.w;
    }
    out[v * 32 + lane] = r;
}

// ---------------- pooling ----------------
__global__ void k_bounds(const int* __restrict__ batch, int* gs, int* ge, int n) {
    int i = blockIdx.x * blockDim.x + threadIdx.x;
    if (i >= n) return;
    int b = batch[i];
    if (i == 0 || batch[i - 1] != b) gs[b] = i;
    if (i == n - 1 || batch[i + 1] != b) ge[b] = i + 1;
}

__global__ void k_pool(const float4* __restrict__ H, float4* __restrict__ pool,
                       const int* __restrict__ gs, const int* __restrict__ ge, int g) {
    int gw = (blockIdx.x * blockDim.x + threadIdx.x) >> 5;
    if (gw >= g) return;
    int lane = threadIdx.x & 31;
    int s = gs[gw], e = ge[gw];
    float4 acc = make_float4(0.f, 0.f, 0.f, 0.f);
    for (int r = s; r < e; r++) {
        float4 v = H[r * 32 + lane];
        acc.x += v.x; acc.y += v.y; acc.z += v.z; acc.w += v.w;
    }
    float sc = (e > s) ? 1.0f / (float)(e - s) : 0.f;
    pool[gw * 32 + lane] = make_float4(acc.x * sc, acc.y * sc, acc.z * sc, acc.w * sc);
}

// ---------------- small GEMM: warp per row ----------------
template <int NPER>
__global__ void k_gemm_small(const float* __restrict__ A, const float* __restrict__ W,
                             const float* __restrict__ bias, float* __restrict__ out,
                             int M, int K, int N, int relu) {
    int gw = (blockIdx.x * blockDim.x + threadIdx.x) >> 5;
    if (gw >= M) return;
    int lane = threadIdx.x & 31;
    float acc[NPER];
    #pragma unroll
    for (int j = 0; j < NPER; j++) acc[j] = 0.f;
    const float* a = A + gw * K;
    for (int k = 0; k < K; k++) {
        float av = __ldg(a + k);
        const float* wr = W + k * N;
        #pragma unroll
        for (int j = 0; j < NPER; j++) acc[j] += av * __ldg(wr + lane + 32 * j);
    }
    #pragma unroll
    for (int j = 0; j < NPER; j++) {
        float v = acc[j] + bias[lane + 32 * j];
        if (relu) v = fmaxf(v, 0.f);
        out[gw * N + lane + 32 * j] = v;
    }
}

// ---------------- batchnorm ----------------
__global__ void k_bn(const float* __restrict__ x, const float* __restrict__ gamma,
                     const float* __restrict__ beta, float* __restrict__ out,
                     int rows, int cols, int relu) {
    int col = blockIdx.x;
    int tid = threadIdx.x, lane = tid & 31, wid = tid >> 5;
    __shared__ float red[8];
    __shared__ float s_m, s_inv;
    float s = 0.f, s2 = 0.f;
    for (int r = tid; r < rows; r += blockDim.x) {
        float v = x[r * cols + col];
        s += v; s2 += v * v;
    }
    #pragma unroll
    for (int o = 16; o; o >>= 1) {
        s  += __shfl_down_sync(0xffffffffu, s, o);
        s2 += __shfl_down_sync(0xffffffffu, s2, o);
    }
    if (lane == 0) { red[wid] = s; red[4 + wid] = s2; }
    __syncthreads();
    if (tid == 0) {
        float ts = red[0] + red[1] + red[2] + red[3];
        float t2 = red[4] + red[5] + red[6] + red[7];
        float m = ts / rows;
        float var = t2 / rows - m * m;
        s_m = m;
        s_inv = rsqrtf(var + 1e-5f);
    }
    __syncthreads();
    float m = s_m, inv = s_inv, ga = gamma[col], be = beta[col];
    for (int r = tid; r < rows; r += blockDim.x) {
        float v = ga * (x[r * cols + col] - m) * inv + be;
        if (relu) v = fmaxf(v, 0.f);
        out[r * cols + col] = v;
    }
}

// ---------------- host orchestration ----------------
struct HeadW {
    const float *Wp1, *bp1, *ga1, *be1, *Wp2, *bp2, *ga2, *be2;
    const float *Wq1, *bq1, *Wq2, *bq2;
};

static void run_encoder_and_head(cudaStream_t st, EncScratch* S,
        const float* x, const int* ei, const int* batch,
        const float* W1, const float* b1, const float* W2, const float* b2,
        const float* W3, const float* b3, const HeadW& hw,
        float* pout, float* zout, int n, int e, int g) {
    const int* src = ei;
    const int* dst = ei + e;

    int tb = 256;
    int nb512 = (n + 511) / 512;
    k_zero  <<<(n + tb - 1) / tb, tb, 0, st>>>(S->cnt, S->gs, S->ge, n, g);
    k_degree<<<(e + tb - 1) / tb, tb, 0, st>>>(dst, S->cnt, e);
    k_part  <<<nb512, 512, 0, st>>>(S->cnt, S->part, n);
    k_scanpart<<<1, NPART, 0, st>>>(S->part, nb512);
    k_off   <<<nb512, 512, 0, st>>>(S->cnt, S->part, S->off, S->dinv, n);
    k_fill  <<<(e + tb - 1) / tb, tb, 0, st>>>(src, dst, S->cnt, S->csr, e);

    int gemm_grid = (n + 63) / 64;
    int gath_grid = (n * 32 + tb - 1) / tb;

    const uint2* Gh = (const uint2*)S->Gh;
    float4* Ha = (float4*)S->Ha;
    float4* Hb = (float4*)S->Hb;

    k_gemm_p2<<<gemm_grid, 256, GEMM_SMEM, st>>>(x, W1, S->Gh, n);
    k_gather<<<gath_grid, tb, 0, st>>>(Gh, b1, nullptr, Ha, S->off, S->csr, S->dinv, n, 0);
    k_gemm_p2<<<gemm_grid, 256, GEMM_SMEM, st>>>(S->Ha, W2, S->Gh, n);
    k_gather<<<gath_grid, tb, 0, st>>>(Gh, b2, (const float4*)Ha, Hb, S->off, S->csr, S->dinv, n, 1);
    k_gemm_p2<<<gemm_grid, 256, GEMM_SMEM, st>>>(S->Hb, W3, S->Gh, n);
    k_gather<<<gath_grid, tb, 0, st>>>(Gh, b3, (const float4*)Hb, Ha, S->off, S->csr, S->dinv, n, 1);

    k_bounds<<<(n + tb - 1) / tb, tb, 0, st>>>(batch, S->gs, S->ge, n);
    k_pool<<<(g * 32 + tb - 1) / tb, tb, 0, st>>>((const float4*)Ha, (float4*)S->pool,
                                                  S->gs, S->ge, g);

    // head
    int gw_blocks = (g * 32 + 255) / 256;
    k_gemm_small<8><<<gw_blocks, 256, 0, st>>>(S->pool, hw.Wp1, hw.bp1, S->t, g, HID, PROJ, 0);
    k_bn<<<PROJ, 128, 0, st>>>(S->t, hw.ga1, hw.be1, S->t, g, PROJ, 1);
    k_gemm_small<8><<<gw_blocks, 256, 0, st>>>(S->t, hw.Wp2, hw.bp2, S->t2, g, PROJ, PROJ, 0);
    k_bn<<<PROJ, 128, 0, st>>>(S->t2, hw.ga2, hw.be2, zout, g, PROJ, 0);
    k_gemm_small<4><<<gw_blocks, 256, 0, st>>>(zout, hw.Wq1, hw.bq1, S->q, g, PROJ, PROJ / 2, 1);
    k_gemm_small<8><<<gw_blocks, 256, 0, st>>>(S->q, hw.Wq2, hw.bq2, pout, g, PROJ / 2, PROJ, 0);
}

extern "C" void kernel_launch(void* const* d_in, const int* in_sizes, int n_in,
                              void* d_out, int out_size) {
    const float* x1  = (const float*)d_in[0];
    const int*   ei1 = (const int*)  d_in[1];
    const int*   bt1 = (const int*)  d_in[2];
    const float* x2  = (const float*)d_in[3];
    const int*   ei2 = (const int*)  d_in[4];
    const int*   bt2 = (const int*)  d_in[5];
    const float* W1  = (const float*)d_in[6];
    const float* b1  = (const float*)d_in[7];
    const float* W2  = (const float*)d_in[8];
    const float* b2  = (const float*)d_in[9];
    const float* W3  = (const float*)d_in[10];
    const float* b3  = (const float*)d_in[11];
    HeadW hw;
    hw.Wp1 = (const float*)d_in[12]; hw.bp1 = (const float*)d_in[13];
    hw.ga1 = (const float*)d_in[14]; hw.be1 = (const float*)d_in[15];
    hw.Wp2 = (const float*)d_in[16]; hw.bp2 = (const float*)d_in[17];
    hw.ga2 = (const float*)d_in[18]; hw.be2 = (const float*)d_in[19];
    hw.Wq1 = (const float*)d_in[20]; hw.bq1 = (const float*)d_in[21];
    hw.Wq2 = (const float*)d_in[22]; hw.bq2 = (const float*)d_in[23];

    int n = in_sizes[0] / INF_;
    int e = in_sizes[1] / 2;
    int g = GG;

    static bool init = false;
    static cudaStream_t s2;
    static cudaEvent_t evFork, evJoin;
    if (!init) {
        cudaStreamCreateWithFlags(&s2, cudaStreamNonBlocking);
        cudaEventCreateWithFlags(&evFork, cudaEventDisableTiming);
        cudaEventCreateWithFlags(&evJoin, cudaEventDisableTiming);
        cudaFuncSetAttribute(k_gemm_p2, cudaFuncAttributeMaxDynamicSharedMemorySize,
                             GEMM_SMEM);
        init = true;
    }

    EncScratch *S0, *S1;
    cudaGetSymbolAddress((void**)&S0, g_e0);
    cudaGetSymbolAddress((void**)&S1, g_e1);

    float* out = (float*)d_out;
    float* p1 = out;
    float* p2 = out + g * PROJ;
    float* z1 = out + 2 * g * PROJ;
    float* z2 = out + 3 * g * PROJ;

    // fork
    cudaEventRecord(evFork, 0);
    cudaStreamWaitEvent(s2, evFork, 0);

    run_encoder_and_head(0,  S0, x1, ei1, bt1, W1, b1, W2, b2, W3, b3, hw, p1, z1, n, e, g);
    run_encoder_and_head(s2, S1, x2, ei2, bt2, W1, b1, W2, b2, W3, b3, hw, p2, z2, n, e, g);

    // join
    cudaEventRecord(evJoin, s2);
    cudaStreamWaitEvent(0, evJoin, 0);
}

// round 11
// speedup vs baseline: 1.4892x; 1.0234x over previous
#include <cuda_runtime.h>
#include <cuda_bf16.h>
#include <cuda_fp16.h>
#include <math.h>

// Problem constants
#define NN 50000
#define EE 1600000
#define GG 512
#define INF_ 128
#define HID 128
#define PROJ 256
#define NPART 128   // >= ceil(NN/512)

// ---------------- device scratch, duplicated per encoder ----------------
// All float4/uint2-cast arrays first (16B-multiple sizes); odd-sized off[] last.
struct alignas(16) EncScratch {
    __half Ph[NN * HID];      // fp16 prescaled features dinv[u]*(A@W)[u]
    float Ha[NN * HID];
    float Hb[NN * HID];
    float pool[GG * HID];
    float t [GG * PROJ];
    float t2[GG * PROJ];
    float q [GG * (PROJ/2)];
    float dinv[NN];
    int   cnt[NN];
    int   csr[EE];
    int   part[NPART];
    int   off[NN + 1];        // odd size -> keep last
};
__device__ EncScratch g_e0;
__device__ EncScratch g_e1;

// ---------------- CSR build ----------------
__global__ void k_zero(int* cnt, int n) {
    int i = blockIdx.x * blockDim.x + threadIdx.x;
    if (i < n) cnt[i] = 0;
}

__global__ void k_degree(const int* __restrict__ dst, int* cnt, int e) {
    int i = blockIdx.x * blockDim.x + threadIdx.x;
    if (i < e) atomicAdd(&cnt[dst[i]], 1);
}

__global__ void k_part(const int* __restrict__ cnt, int* part, int n) {
    __shared__ int red[16];
    int i = blockIdx.x * blockDim.x + threadIdx.x;
    int v = (i < n) ? cnt[i] : 0;
    int lane = threadIdx.x & 31, wid = threadIdx.x >> 5;
    #pragma unroll
    for (int o = 16; o; o >>= 1) v += __shfl_down_sync(0xffffffffu, v, o);
    if (lane == 0) red[wid] = v;
    __syncthreads();
    if (wid == 0) {
        int s = (lane < (blockDim.x >> 5)) ? red[lane] : 0;
        #pragma unroll
        for (int o = 16; o; o >>= 1) s += __shfl_down_sync(0xffffffffu, s, o);
        if (lane == 0) part[blockIdx.x] = s;
    }
}

__global__ void k_scanpart(int* part, int nb) {
    __shared__ int sh[NPART];
    int tid = threadIdx.x;
    sh[tid] = (tid < nb) ? part[tid] : 0;
    __syncthreads();
    for (int d = 1; d < NPART; d <<= 1) {
        int v = (tid >= d) ? sh[tid - d] : 0;
        __syncthreads();
        sh[tid] += v;
        __syncthreads();
    }
    if (tid < nb) part[tid] = (tid == 0) ? 0 : sh[tid - 1];
}

__global__ void k_off(int* cnt, const int* __restrict__ part, int* off,
                      float* dinv, int n) {
    __shared__ int wsum[16];
    int i = blockIdx.x * blockDim.x + threadIdx.x;
    int lane = threadIdx.x & 31, wid = threadIdx.x >> 5;
    int nw = blockDim.x >> 5;
    int v = (i < n) ? cnt[i] : 0;
    int x = v;
    #pragma unroll
    for (int d = 1; d < 32; d <<= 1) {
        int y = __shfl_up_sync(0xffffffffu, x, d);
        if (lane >= d) x += y;
    }
    if (lane == 31) wsum[wid] = x;
    __syncthreads();
    if (wid == 0) {
        int s = (lane < nw) ? wsum[lane] : 0;
        #pragma unroll
        for (int d = 1; d < 32; d <<= 1) {
            int y = __shfl_up_sync(0xffffffffu, s, d);
            if (lane >= d) s += y;
        }
        wsum[lane] = s;
    }
    __syncthreads();
    int excl = x - v + ((wid == 0) ? 0 : wsum[wid - 1]) + part[blockIdx.x];
    if (i < n) {
        off[i]  = excl;
        dinv[i] = rsqrtf((float)(v + 1));
        cnt[i]  = excl;          // cursor for fill
        if (i == n - 1) off[n] = excl + v;
    }
}

__global__ void k_fill(const int* __restrict__ src, const int* __restrict__ dst,
                       int* cnt, int* csr, int e) {
    int i = blockIdx.x * blockDim.x + threadIdx.x;
    if (i < e) {
        int d = dst[i];
        int pos = atomicAdd(&cnt[d], 1);
        csr[pos] = src[i];
    }
}

// ---------------- packed-f32x2 GEMM + dinv prescale + fp16 epilogue ---------
// out_h[r][c] = half( dinv[r] * (A[r,:]@W[:,c]) )
__device__ __forceinline__ void fma_f32x2(unsigned long long& d,
                                          unsigned long long a,
                                          unsigned long long b) {
    asm("fma.rn.f32x2 %0, %1, %2, %0;" : "+l"(d) : "l"(a), "l"(b));
}

__global__ __launch_bounds__(256) void k_gemm_p2(
        const float* __restrict__ A, const float* __restrict__ W,
        const float* __restrict__ dinv, __half* __restrict__ out, int M) {
    extern __shared__ float sm[];
    float2* Ws2 = (float2*)sm;            // [64][128] float2 = 64KB
    float*  As  = sm + 64 * 128 * 2;      // [64][128] float  = 32KB
    int tid = threadIdx.x;

    // Load W interleaved by k-pairs: Ws2[kp][c] = (W[2kp][c], W[2kp+1][c])
    for (int i = tid; i < 64 * 32; i += 256) {
        int kp = i >> 5, c4 = i & 31;
        float4 w0 = ((const float4*)W)[(2 * kp)     * 32 + c4];
        float4 w1 = ((const float4*)W)[(2 * kp + 1) * 32 + c4];
        float2* dstp = Ws2 + kp * 128 + (c4 << 2);
        dstp[0] = make_float2(w0.x, w1.x);
        dstp[1] = make_float2(w0.y, w1.y);
        dstp[2] = make_float2(w0.z, w1.z);
        dstp[3] = make_float2(w0.w, w1.w);
    }
    int rowbase = blockIdx.x * 64;
    for (int i = tid; i < 64 * 32; i += 256) {
        int r = i >> 5, c4 = i & 31;
        float4 v = make_float4(0.f, 0.f, 0.f, 0.f);
        if (rowbase + r < M) v = ((const float4*)A)[(rowbase + r) * 32 + c4];
        *(float4*)(As + r * 128 + (c4 << 2)) = v;
    }
    __syncthreads();

    int lane = tid & 31, w = tid >> 5;
    unsigned long long acc[8][4];
    #pragma unroll
    for (int r = 0; r < 8; r++)
        #pragma unroll
        for (int j = 0; j < 4; j++) acc[r][j] = 0ull;   // (0.0f, 0.0f)

    const unsigned long long* Wsu = (const unsigned long long*)Ws2;
    #pragma unroll 4
    for (int kp = 0; kp < 64; kp++) {
        unsigned long long w2[4];
        #pragma unroll
        for (int j = 0; j < 4; j++) w2[j] = Wsu[kp * 128 + lane + 32 * j];
        #pragma unroll
        for (int r = 0; r < 8; r++) {
            unsigned long long a2 =
                *(const unsigned long long*)(As + (w + r * 8) * 128 + 2 * kp);
            #pragma unroll
            for (int j = 0; j < 4; j++) fma_f32x2(acc[r][j], a2, w2[j]);
        }
    }

    #pragma unroll
    for (int r = 0; r < 8; r++) {
        int row = rowbase + w + r * 8;
        if (row < M) {
            float dv = dinv[row];
            #pragma unroll
            for (int j = 0; j < 4; j++) {
                unsigned long long u = acc[r][j];
                float lo = __uint_as_float((unsigned int)(u & 0xffffffffu));
                float hi = __uint_as_float((unsigned int)(u >> 32));
                out[row * 128 + lane + 32 * j] = __float2half_rn(dv * (lo + hi));
            }
        }
    }
}
#define GEMM_SMEM ((64 * 128 * 2 + 64 * 128) * sizeof(float))

// ---------------- gather: warp per node, prescaled fp16 features ------------
// out[v] = relu( dinv[v] * (sum_{u in N(v)} P[u] + P[v]) + bias ) [+ residual]
__global__ void k_gather(const uint2* __restrict__ P, const float* __restrict__ bias,
                         const float4* __restrict__ Hres, float4* __restrict__ out,
                         const int* __restrict__ off, const int* __restrict__ csr,
                         const float* __restrict__ dinv, int n, int mode) {
    int gw = (blockIdx.x * blockDim.x + threadIdx.x) >> 5;
    if (gw >= n) return;
    int lane = threadIdx.x & 31;
    int v = gw;
    int off0 = off[v], off1 = off[v + 1];
    float dv = dinv[v];
    uint2 bu = P[v * 32 + lane];
    const __half2* bh = (const __half2*)&bu;
    float2 b0 = __half22float2(bh[0]);
    float2 b1 = __half22float2(bh[1]);
    float4 acc = make_float4(b0.x, b0.y, b1.x, b1.y);   // self term P[v]
    for (int j = off0; j < off1; j += 32) {
        int idx = j + lane;
        int u = (idx < off1) ? csr[idx] : 0;
        int m = off1 - j; if (m > 32) m = 32;
        #pragma unroll 4
        for (int i = 0; i < m; i++) {
            int uu = __shfl_sync(0xffffffffu, u, i);
            uint2 hu = P[uu * 32 + lane];
            const __half2* hh = (const __half2*)&hu;
            float2 f0 = __half22float2(hh[0]);
            float2 f1 = __half22float2(hh[1]);
            acc.x += f0.x; acc.y += f0.y;
            acc.z += f1.x; acc.w += f1.y;
        }
    }
    const float4* b4 = (const float4*)bias;
    float4 bb = b4[lane];
    float4 r;
    r.x = fmaxf(fmaf(dv, acc.x, bb.x), 0.f);
    r.y = fmaxf(fmaf(dv, acc.y, bb.y), 0.f);
    r.z = fmaxf(fmaf(dv, acc.z, bb.z), 0.f);
    r.w = fmaxf(fmaf(dv, acc.w, bb.w), 0.f);
    if (mode == 1) {
        float4 h = Hres[v * 32 + lane];
        r.x += h.x; r.y += h.y; r.z += h.z; r.w += h.w;
    }
    out[v * 32 + lane] = r;
}

// ---------------- pooling (binary-search bounds, no aux kernels) ------------
__global__ void k_pool(const float4* __restrict__ H, float4* __restrict__ pool,
                       const int* __restrict__ batch, int n, int g) {
    int gw = (blockIdx.x * blockDim.x + threadIdx.x) >> 5;
    if (gw >= g) return;
    int lane = threadIdx.x & 31;
    // lower_bound(batch, gw) and lower_bound(batch, gw+1)
    int lo = 0, hi = n;
    while (lo < hi) { int mid = (lo + hi) >> 1; if (batch[mid] < gw) lo = mid + 1; else hi = mid; }
    int s = lo;
    hi = n;
    while (lo < hi) { int mid = (lo + hi) >> 1; if (batch[mid] < gw + 1) lo = mid + 1; else hi = mid; }
    int e = lo;
    float4 acc = make_float4(0.f, 0.f, 0.f, 0.f);
    for (int r = s; r < e; r++) {
        float4 v = H[r * 32 + lane];
        acc.x += v.x; acc.y += v.y; acc.z += v.z; acc.w += v.w;
    }
    float sc = (e > s) ? 1.0f / (float)(e - s) : 0.f;
    pool[gw * 32 + lane] = make_float4(acc.x * sc, acc.y * sc, acc.z * sc, acc.w * sc);
}

// ---------------- small GEMM: warp per row ----------------
template <int NPER>
__global__ void k_gemm_small(const float* __restrict__ A, const float* __restrict__ W,
                             const float* __restrict__ bias, float* __restrict__ out,
                             int M, int K, int N, int relu) {
    int gw = (blockIdx.x * blockDim.x + threadIdx.x) >> 5;
    if (gw >= M) return;
    int lane = threadIdx.x & 31;
    float acc[NPER];
    #pragma unroll
    for (int j = 0; j < NPER; j++) acc[j] = 0.f;
    const float* a = A + gw * K;
    for (int k = 0; k < K; k++) {
        float av = __ldg(a + k);
        const float* wr = W + k * N;
        #pragma unroll
        for (int j = 0; j < NPER; j++) acc[j] += av * __ldg(wr + lane + 32 * j);
    }
    #pragma unroll
    for (int j = 0; j < NPER; j++) {
        float v = acc[j] + bias[lane + 32 * j];
        if (relu) v = fmaxf(v, 0.f);
        out[gw * N + lane + 32 * j] = v;
    }
}

// ---------------- batchnorm ----------------
__global__ void k_bn(const float* __restrict__ x, const float* __restrict__ gamma,
                     const float* __restrict__ beta, float* __restrict__ out,
                     int rows, int cols, int relu) {
    int col = blockIdx.x;
    int tid = threadIdx.x, lane = tid & 31, wid = tid >> 5;
    __shared__ float red[8];
    __shared__ float s_m, s_inv;
    float s = 0.f, s2 = 0.f;
    for (int r = tid; r < rows; r += blockDim.x) {
        float v = x[r * cols + col];
        s += v; s2 += v * v;
    }
    #pragma unroll
    for (int o = 16; o; o >>= 1) {
        s  += __shfl_down_sync(0xffffffffu, s, o);
        s2 += __shfl_down_sync(0xffffffffu, s2, o);
    }
    if (lane == 0) { red[wid] = s; red[4 + wid] = s2; }
    __syncthreads();
    if (tid == 0) {
        float ts = red[0] + red[1] + red[2] + red[3];
        float t2 = red[4] + red[5] + red[6] + red[7];
        float m = ts / rows;
        float var = t2 / rows - m * m;
        s_m = m;
        s_inv = rsqrtf(var + 1e-5f);
    }
    __syncthreads();
    float m = s_m, inv = s_inv, ga = gamma[col], be = beta[col];
    for (int r = tid; r < rows; r += blockDim.x) {
        float v = ga * (x[r * cols + col] - m) * inv + be;
        if (relu) v = fmaxf(v, 0.f);
        out[r * cols + col] = v;
    }
}

// ---------------- host orchestration ----------------
struct HeadW {
    const float *Wp1, *bp1, *ga1, *be1, *Wp2, *bp2, *ga2, *be2;
    const float *Wq1, *bq1, *Wq2, *bq2;
};

static void run_encoder_and_head(cudaStream_t st, EncScratch* S,
        const float* x, const int* ei, const int* batch,
        const float* W1, const float* b1, const float* W2, const float* b2,
        const float* W3, const float* b3, const HeadW& hw,
        float* pout, float* zout, int n, int e, int g) {
    const int* src = ei;
    const int* dst = ei + e;

    int tb = 256;
    int nb512 = (n + 511) / 512;
    k_zero  <<<(n + tb - 1) / tb, tb, 0, st>>>(S->cnt, n);
    k_degree<<<(e + tb - 1) / tb, tb, 0, st>>>(dst, S->cnt, e);
    k_part  <<<nb512, 512, 0, st>>>(S->cnt, S->part, n);
    k_scanpart<<<1, NPART, 0, st>>>(S->part, nb512);
    k_off   <<<nb512, 512, 0, st>>>(S->cnt, S->part, S->off, S->dinv, n);
    k_fill  <<<(e + tb - 1) / tb, tb, 0, st>>>(src, dst, S->cnt, S->csr, e);

    int gemm_grid = (n + 63) / 64;
    int gath_grid = (n * 32 + tb - 1) / tb;

    const uint2* Ph = (const uint2*)S->Ph;
    float4* Ha = (float4*)S->Ha;
    float4* Hb = (float4*)S->Hb;

    k_gemm_p2<<<gemm_grid, 256, GEMM_SMEM, st>>>(x, W1, S->dinv, S->Ph, n);
    k_gather<<<gath_grid, tb, 0, st>>>(Ph, b1, nullptr, Ha, S->off, S->csr, S->dinv, n, 0);
    k_gemm_p2<<<gemm_grid, 256, GEMM_SMEM, st>>>(S->Ha, W2, S->dinv, S->Ph, n);
    k_gather<<<gath_grid, tb, 0, st>>>(Ph, b2, (const float4*)Ha, Hb, S->off, S->csr, S->dinv, n, 1);
    k_gemm_p2<<<gemm_grid, 256, GEMM_SMEM, st>>>(S->Hb, W3, S->dinv, S->Ph, n);
    k_gather<<<gath_grid, tb, 0, st>>>(Ph, b3, (const float4*)Hb, Ha, S->off, S->csr, S->dinv, n, 1);

    k_pool<<<(g * 32 + tb - 1) / tb, tb, 0, st>>>((const float4*)Ha, (float4*)S->pool,
                                                  batch, n, g);

    // head
    int gw_blocks = (g * 32 + 255) / 256;
    k_gemm_small<8><<<gw_blocks, 256, 0, st>>>(S->pool, hw.Wp1, hw.bp1, S->t, g, HID, PROJ, 0);
    k_bn<<<PROJ, 128, 0, st>>>(S->t, hw.ga1, hw.be1, S->t, g, PROJ, 1);
    k_gemm_small<8><<<gw_blocks, 256, 0, st>>>(S->t, hw.Wp2, hw.bp2, S->t2, g, PROJ, PROJ, 0);
    k_bn<<<PROJ, 128, 0, st>>>(S->t2, hw.ga2, hw.be2, zout, g, PROJ, 0);
    k_gemm_small<4><<<gw_blocks, 256, 0, st>>>(zout, hw.Wq1, hw.bq1, S->q, g, PROJ, PROJ / 2, 1);
    k_gemm_small<8><<<gw_blocks, 256, 0, st>>>(S->q, hw.Wq2, hw.bq2, pout, g, PROJ / 2, PROJ, 0);
}

extern "C" void kernel_launch(void* const* d_in, const int* in_sizes, int n_in,
                              void* d_out, int out_size) {
    const float* x1  = (const float*)d_in[0];
    const int*   ei1 = (const int*)  d_in[1];
    const int*   bt1 = (const int*)  d_in[2];
    const float* x2  = (const float*)d_in[3];
    const int*   ei2 = (const int*)  d_in[4];
    const int*   bt2 = (const int*)  d_in[5];
    const float* W1  = (const float*)d_in[6];
    const float* b1  = (const float*)d_in[7];
    const float* W2  = (const float*)d_in[8];
    const float* b2  = (const float*)d_in[9];
    const float* W3  = (const float*)d_in[10];
    const float* b3  = (const float*)d_in[11];
    HeadW hw;
    hw.Wp1 = (const float*)d_in[12]; hw.bp1 = (const float*)d_in[13];
    hw.ga1 = (const float*)d_in[14]; hw.be1 = (const float*)d_in[15];
    hw.Wp2 = (const float*)d_in[16]; hw.bp2 = (const float*)d_in[17];
    hw.ga2 = (const float*)d_in[18]; hw.be2 = (const float*)d_in[19];
    hw.Wq1 = (const float*)d_in[20]; hw.bq1 = (const float*)d_in[21];
    hw.Wq2 = (const float*)d_in[22]; hw.bq2 = (const float*)d_in[23];

    int n = in_sizes[0] / INF_;
    int e = in_sizes[1] / 2;
    int g = GG;

    static bool init = false;
    static cudaStream_t s2;
    static cudaEvent_t evFork, evJoin;
    if (!init) {
        cudaStreamCreateWithFlags(&s2, cudaStreamNonBlocking);
        cudaEventCreateWithFlags(&evFork, cudaEventDisableTiming);
        cudaEventCreateWithFlags(&evJoin, cudaEventDisableTiming);
        cudaFuncSetAttribute(k_gemm_p2, cudaFuncAttributeMaxDynamicSharedMemorySize,
                             GEMM_SMEM);
        init = true;
    }

    EncScratch *S0, *S1;
    cudaGetSymbolAddress((void**)&S0, g_e0);
    cudaGetSymbolAddress((void**)&S1, g_e1);

    float* out = (float*)d_out;
    float* p1 = out;
    float* p2 = out + g * PROJ;
    float* z1 = out + 2 * g * PROJ;
    float* z2 = out + 3 * g * PROJ;

    // fork
    cudaEventRecord(evFork, 0);
    cudaStreamWaitEvent(s2, evFork, 0);

    run_encoder_and_head(0,  S0, x1, ei1, bt1, W1, b1, W2, b2, W3, b3, hw, p1, z1, n, e, g);
    run_encoder_and_head(s2, S1, x2, ei2, bt2, W1, b1, W2, b2, W3, b3, hw, p2, z2, n, e, g);

    // join
    cudaEventRecord(evJoin, s2);
    cudaStreamWaitEvent(0, evJoin, 0);
}